// round 1
// baseline (speedup 1.0000x reference)
#include <cuda_runtime.h>
#include <math_constants.h>

#define BB 2
#define SS 2048
#define DD 1024
#define HH 16
#define DHD 64
#define MTOT (BB*SS)   // 4096
#define COUT 512

// ---------------- scratch (device globals; no allocation allowed) -------------
__device__ float g_q [BB*HH*SS*DHD];   // [B,H,S,DH]
__device__ float g_km[BB*HH*SS*DHD];   // merged K: (1-g)*kh + g*(conv+bias)
__device__ float g_v [BB*HH*SS*DHD];
__device__ float g_ao[BB*SS*DD];       // attention out, [B,S,D]
__device__ float g_wt0[3*COUT*DD];     // conv w0 transposed: [t][co][ci]
__device__ float g_wt1[5*COUT*DD];

__device__ __forceinline__ float sigm(float x){ return 1.0f/(1.0f+__expf(-x)); }

// ---------------- weight transpose for conv (t-major) ------------------------
__global__ void prep_wt(const float* __restrict__ w0, const float* __restrict__ w1){
    int idx = blockIdx.x*blockDim.x + threadIdx.x;
    const int tot0 = 3*COUT*DD;
    const int tot1 = 5*COUT*DD;
    if (idx < tot0){
        int t = idx/(COUT*DD); int r = idx%(COUT*DD);
        int co = r/DD, ci = r%DD;
        g_wt0[idx] = w0[(co*DD+ci)*3 + t];
    }
    if (idx < tot1){
        int t = idx/(COUT*DD); int r = idx%(COUT*DD);
        int co = r/DD, ci = r%DD;
        g_wt1[idx] = w1[(co*DD+ci)*5 + t];
    }
}

// ---------------- 128x128x16 NT GEMM: Y = X @ W^T ----------------------------
// MODE 0: dst = g_q (head layout)
// MODE 1: dst = g_km, scaled by (1 - sigmoid(gate[h]))
// MODE 3: dst = g_v (head layout)
// MODE 2: dst = out param, plain [m,n] + bias; X = g_ao
#define LDA 132
template<int MODE>
__global__ __launch_bounds__(256) void gemm_nt(const float* __restrict__ X,
                                               const float* __restrict__ W,
                                               float* __restrict__ dstp,
                                               const float* __restrict__ aux){
    __shared__ float As[16][LDA];
    __shared__ float Bs[16][LDA];
    const int m0 = blockIdx.y*128, n0 = blockIdx.x*128;
    const int tid = threadIdx.x;
    const int tx = tid & 15, ty = tid >> 4;
    const int lr = tid >> 2, lc = (tid & 3)*4;

    const float* Xp = (MODE==2) ? g_ao : X;

    float acc[8][8];
    #pragma unroll
    for (int i=0;i<8;i++)
        #pragma unroll
        for (int j=0;j<8;j++) acc[i][j]=0.0f;

    for (int k0=0; k0<DD; k0+=16){
        #pragma unroll
        for (int h2=0; h2<2; h2++){
            int row = m0 + lr + h2*64;
            float4 a = *(const float4*)&Xp[row*DD + k0 + lc];
            As[lc+0][lr+h2*64]=a.x; As[lc+1][lr+h2*64]=a.y;
            As[lc+2][lr+h2*64]=a.z; As[lc+3][lr+h2*64]=a.w;
            int rowb = n0 + lr + h2*64;
            float4 b = *(const float4*)&W[rowb*DD + k0 + lc];
            Bs[lc+0][lr+h2*64]=b.x; Bs[lc+1][lr+h2*64]=b.y;
            Bs[lc+2][lr+h2*64]=b.z; Bs[lc+3][lr+h2*64]=b.w;
        }
        __syncthreads();
        #pragma unroll
        for (int kk=0; kk<16; kk++){
            float4 a0 = *(const float4*)&As[kk][ty*4];
            float4 a1 = *(const float4*)&As[kk][64+ty*4];
            float4 b0 = *(const float4*)&Bs[kk][tx*4];
            float4 b1 = *(const float4*)&Bs[kk][64+tx*4];
            float ar[8] = {a0.x,a0.y,a0.z,a0.w,a1.x,a1.y,a1.z,a1.w};
            float br[8] = {b0.x,b0.y,b0.z,b0.w,b1.x,b1.y,b1.z,b1.w};
            #pragma unroll
            for (int i=0;i<8;i++)
                #pragma unroll
                for (int j=0;j<8;j++) acc[i][j] = fmaf(ar[i], br[j], acc[i][j]);
        }
        __syncthreads();
    }

    float* dst = (MODE==0) ? g_q : (MODE==1) ? g_km : (MODE==3) ? g_v : dstp;

    #pragma unroll
    for (int i=0;i<8;i++){
        int m = m0 + ((i<4) ? (ty*4+i) : (64+ty*4+i-4));
        int bidx = m >> 11;           // /S
        int s    = m & (SS-1);
        #pragma unroll
        for (int jg=0; jg<2; jg++){
            int n = n0 + ((jg==0) ? tx*4 : 64+tx*4);
            float4 v;
            v.x = acc[i][jg*4+0]; v.y = acc[i][jg*4+1];
            v.z = acc[i][jg*4+2]; v.w = acc[i][jg*4+3];
            if (MODE==2){
                v.x += aux[n+0]; v.y += aux[n+1]; v.z += aux[n+2]; v.w += aux[n+3];
                *(float4*)&dst[m*DD + n] = v;
            } else {
                int h = n >> 6, d = n & 63;
                if (MODE==1){
                    float gsc = 1.0f - sigm(aux[h]);
                    v.x*=gsc; v.y*=gsc; v.z*=gsc; v.w*=gsc;
                }
                *(float4*)&dst[((bidx*HH+h)*SS + s)*DHD + d] = v;
            }
        }
    }
}

// ---------------- conv-as-GEMM, accumulates g*conv into g_km ------------------
__global__ __launch_bounds__(256) void conv_gemm(const float* __restrict__ kin,
                                                 const float* __restrict__ cb0,
                                                 const float* __restrict__ cb1,
                                                 const float* __restrict__ gate){
    __shared__ float As[16][LDA];
    __shared__ float Bs[16][LDA];
    const int branch = blockIdx.x >> 2;
    const int n0 = (blockIdx.x & 3)*128;
    const int m0 = blockIdx.y*128;
    const float* wt   = branch ? g_wt1 : g_wt0;
    const float* bias = branch ? cb1 : cb0;
    const int ksz = branch ? 5 : 3;
    const int pad = ksz >> 1;
    const int Kp  = ksz << 10;

    const int tid = threadIdx.x;
    const int tx = tid & 15, ty = tid >> 4;
    const int lr = tid >> 2, lc = (tid & 3)*4;

    float acc[8][8];
    #pragma unroll
    for (int i=0;i<8;i++)
        #pragma unroll
        for (int j=0;j<8;j++) acc[i][j]=0.0f;

    for (int k0=0; k0<Kp; k0+=16){
        int t   = k0 >> 10;        // constant across 16-wide tile (16 | 1024)
        int ci0 = k0 & 1023;
        int shift = t - pad;
        #pragma unroll
        for (int h2=0; h2<2; h2++){
            int m = m0 + lr + h2*64;
            int bidx = m >> 11;
            int s = (m & (SS-1)) + shift;
            float4 a = make_float4(0.f,0.f,0.f,0.f);
            if (s >= 0 && s < SS)
                a = *(const float4*)&kin[(bidx*SS + s)*DD + ci0 + lc];
            As[lc+0][lr+h2*64]=a.x; As[lc+1][lr+h2*64]=a.y;
            As[lc+2][lr+h2*64]=a.z; As[lc+3][lr+h2*64]=a.w;
            int co = n0 + lr + h2*64;
            float4 b = *(const float4*)&wt[(t*COUT+co)*DD + ci0 + lc];
            Bs[lc+0][lr+h2*64]=b.x; Bs[lc+1][lr+h2*64]=b.y;
            Bs[lc+2][lr+h2*64]=b.z; Bs[lc+3][lr+h2*64]=b.w;
        }
        __syncthreads();
        #pragma unroll
        for (int kk=0; kk<16; kk++){
            float4 a0 = *(const float4*)&As[kk][ty*4];
            float4 a1 = *(const float4*)&As[kk][64+ty*4];
            float4 b0 = *(const float4*)&Bs[kk][tx*4];
            float4 b1 = *(const float4*)&Bs[kk][64+tx*4];
            float ar[8] = {a0.x,a0.y,a0.z,a0.w,a1.x,a1.y,a1.z,a1.w};
            float br[8] = {b0.x,b0.y,b0.z,b0.w,b1.x,b1.y,b1.z,b1.w};
            #pragma unroll
            for (int i=0;i<8;i++)
                #pragma unroll
                for (int j=0;j<8;j++) acc[i][j] = fmaf(ar[i], br[j], acc[i][j]);
        }
        __syncthreads();
    }

    #pragma unroll
    for (int i=0;i<8;i++){
        int m = m0 + ((i<4) ? (ty*4+i) : (64+ty*4+i-4));
        int bidx = m >> 11;
        int s    = m & (SS-1);
        #pragma unroll
        for (int jg=0; jg<2; jg++){
            int co = n0 + ((jg==0) ? tx*4 : 64+tx*4);
            int gc = branch*COUT + co;
            int h = gc >> 6, d = gc & 63;
            float g = sigm(gate[h]);
            float4* p = (float4*)&g_km[((bidx*HH+h)*SS + s)*DHD + d];
            float4 old = *p;
            old.x += g*(acc[i][jg*4+0] + bias[co+0]);
            old.y += g*(acc[i][jg*4+1] + bias[co+1]);
            old.z += g*(acc[i][jg*4+2] + bias[co+2]);
            old.w += g*(acc[i][jg*4+3] + bias[co+3]);
            *p = old;
        }
    }
}

// ---------------- flash attention (64-row q tiles, online softmax) ------------
#define LDP 68
__global__ __launch_bounds__(256) void flash_attn(const int* __restrict__ mask){
    extern __shared__ float sm[];
    float (*Qs)[LDP] = (float(*)[LDP])(sm);              // [d][m]
    float (*Ks)[LDP] = (float(*)[LDP])(sm +   64*LDP);   // [d][n]
    float (*Vs)[LDP] = (float(*)[LDP])(sm + 2*64*LDP);   // [jk][d]
    float (*Ps)[LDP] = (float(*)[LDP])(sm + 3*64*LDP);   // [jk][m]

    const int bh = blockIdx.y;
    const int bidx = bh >> 4, h = bh & 15;
    const int q0 = blockIdx.x*64;
    const int tid = threadIdx.x;
    const int tx = tid & 15, ty = tid >> 4;
    const int lr = tid >> 2, lc4 = tid & 3;

    const float* Qg = g_q  + (size_t)bh*SS*DHD;
    const float* Kg = g_km + (size_t)bh*SS*DHD;
    const float* Vg = g_v  + (size_t)bh*SS*DHD;

    #pragma unroll
    for (int jj=0; jj<4; jj++){
        int c = (lc4 + jj*4)*4;
        float4 qv = *(const float4*)&Qg[(q0+lr)*DHD + c];
        Qs[c+0][lr]=qv.x; Qs[c+1][lr]=qv.y; Qs[c+2][lr]=qv.z; Qs[c+3][lr]=qv.w;
    }

    float m_run[4] = {-CUDART_INF_F,-CUDART_INF_F,-CUDART_INF_F,-CUDART_INF_F};
    float l_run[4] = {0.f,0.f,0.f,0.f};
    float o[4][4];
    #pragma unroll
    for (int i=0;i<4;i++)
        #pragma unroll
        for (int j=0;j<4;j++) o[i][j]=0.f;

    const float scl = 0.125f;   // 1/sqrt(64)
    const float NEG = -1e9f;

    for (int kb=0; kb<SS/64; kb++){
        int k0 = kb*64;
        #pragma unroll
        for (int jj=0; jj<4; jj++){
            int c = (lc4 + jj*4)*4;
            float4 kv = *(const float4*)&Kg[(k0+lr)*DHD + c];
            Ks[c+0][lr]=kv.x; Ks[c+1][lr]=kv.y; Ks[c+2][lr]=kv.z; Ks[c+3][lr]=kv.w;
            float4 vv = *(const float4*)&Vg[(k0+lr)*DHD + c];
            *(float4*)&Vs[lr][c] = vv;
        }
        __syncthreads();

        float sc[4][4];
        #pragma unroll
        for (int i=0;i<4;i++)
            #pragma unroll
            for (int j=0;j<4;j++) sc[i][j]=0.f;

        #pragma unroll 16
        for (int kt=0; kt<64; kt++){
            float4 aq = *(const float4*)&Qs[kt][ty*4];
            float4 bk = *(const float4*)&Ks[kt][tx*4];
            float ar[4]={aq.x,aq.y,aq.z,aq.w};
            float br[4]={bk.x,bk.y,bk.z,bk.w};
            #pragma unroll
            for (int i=0;i<4;i++)
                #pragma unroll
                for (int j=0;j<4;j++) sc[i][j] = fmaf(ar[i], br[j], sc[i][j]);
        }

        // mask + scale
        #pragma unroll
        for (int i=0;i<4;i++){
            const int4 mr = *(const int4*)&mask[((size_t)bidx*SS + q0+ty*4+i)*SS + k0 + tx*4];
            sc[i][0] = mr.x ? sc[i][0]*scl : NEG;
            sc[i][1] = mr.y ? sc[i][1]*scl : NEG;
            sc[i][2] = mr.z ? sc[i][2]*scl : NEG;
            sc[i][3] = mr.w ? sc[i][3]*scl : NEG;
        }

        // online softmax (row groups: 16 threads sharing ty within a warp)
        #pragma unroll
        for (int i=0;i<4;i++){
            float rm = fmaxf(fmaxf(sc[i][0],sc[i][1]), fmaxf(sc[i][2],sc[i][3]));
            #pragma unroll
            for (int off=8; off>=1; off>>=1)
                rm = fmaxf(rm, __shfl_xor_sync(0xffffffffu, rm, off));
            float mnew = fmaxf(m_run[i], rm);
            float corr = __expf(m_run[i] - mnew);
            float ps = 0.f;
            #pragma unroll
            for (int j=0;j<4;j++){
                float p = __expf(sc[i][j] - mnew);
                Ps[tx*4+j][ty*4+i] = p;
                ps += p;
            }
            #pragma unroll
            for (int off=8; off>=1; off>>=1)
                ps += __shfl_xor_sync(0xffffffffu, ps, off);
            l_run[i] = l_run[i]*corr + ps;
            m_run[i] = mnew;
            o[i][0]*=corr; o[i][1]*=corr; o[i][2]*=corr; o[i][3]*=corr;
        }
        __syncthreads();

        #pragma unroll 16
        for (int jk=0; jk<64; jk++){
            float4 pp = *(const float4*)&Ps[jk][ty*4];
            float4 vv = *(const float4*)&Vs[jk][tx*4];
            float pr[4]={pp.x,pp.y,pp.z,pp.w};
            float vr[4]={vv.x,vv.y,vv.z,vv.w};
            #pragma unroll
            for (int i=0;i<4;i++)
                #pragma unroll
                for (int j=0;j<4;j++) o[i][j] = fmaf(pr[i], vr[j], o[i][j]);
        }
        __syncthreads();
    }

    #pragma unroll
    for (int i=0;i<4;i++){
        float inv = 1.0f / l_run[i];
        int srow = q0 + ty*4 + i;
        float4 v;
        v.x=o[i][0]*inv; v.y=o[i][1]*inv; v.z=o[i][2]*inv; v.w=o[i][3]*inv;
        *(float4*)&g_ao[((size_t)bidx*SS + srow)*DD + h*DHD + tx*4] = v;
    }
}

// ---------------- launch ------------------------------------------------------
extern "C" void kernel_launch(void* const* d_in, const int* in_sizes, int n_in,
                              void* d_out, int out_size){
    const float* q    = (const float*)d_in[0];
    const float* k    = (const float*)d_in[1];
    const float* v    = (const float*)d_in[2];
    const int*   mask = (const int*)  d_in[3];
    const float* Wq   = (const float*)d_in[4];
    const float* Wk   = (const float*)d_in[5];
    const float* Wv   = (const float*)d_in[6];
    const float* Wo   = (const float*)d_in[7];
    const float* bo   = (const float*)d_in[8];
    const float* cw0  = (const float*)d_in[9];
    const float* cb0  = (const float*)d_in[10];
    const float* cw1  = (const float*)d_in[11];
    const float* cb1  = (const float*)d_in[12];
    const float* gate = (const float*)d_in[13];
    float* out = (float*)d_out;

    dim3 blk(256);
    dim3 gproj(DD/128, MTOT/128);   // (8, 32)

    prep_wt<<<(5*COUT*DD + 255)/256, 256>>>(cw0, cw1);
    gemm_nt<0><<<gproj, blk>>>(q, Wq, nullptr, nullptr);
    gemm_nt<1><<<gproj, blk>>>(k, Wk, nullptr, gate);
    gemm_nt<3><<<gproj, blk>>>(v, Wv, nullptr, nullptr);
    conv_gemm<<<dim3(8,32), blk>>>(k, cb0, cb1, gate);

    int smem = 4*64*LDP*sizeof(float);  // ~69.6 KB
    cudaFuncSetAttribute(flash_attn, cudaFuncAttributeMaxDynamicSharedMemorySize, smem);
    flash_attn<<<dim3(SS/64, BB*HH), blk, smem>>>(mask);

    gemm_nt<2><<<gproj, blk>>>(nullptr, Wo, out, bo);
}